// round 14
// baseline (speedup 1.0000x reference)
#include <cuda_runtime.h>
#include <cstdint>

// ---------------------------------------------------------------------------
// GroupVectorAttention — R11 structure (best: 816us) + persistent fused
// kernel (constants loaded once per CTA, 296 CTAs loop over 4096 tiles) +
// cross-subpass B prefetch (next matrix's first chunks issued before each
// epilogue). Mainloops byte-identical to R11.
// ---------------------------------------------------------------------------

#define EPSV 1e-5f

static constexpr int Bb = 4, Nn = 4096, Mm = 16, Cd = 256;
static constexpr int R_ = Bb * Nn * Mm;       // 262144
static constexpr int BNp = Bb * Nn;           // 16384
static constexpr int STAT_BLOCKS = 256;
static constexpr int NTILES = R_ / 64;        // 4096 fused tiles
static constexpr int PGRID = 148;             // persistent final-GEMM CTAs
static constexpr int FGRID = 296;             // persistent fused CTAs (2/SM)

// ---- standalone GEMM smem (u32): A 2x1024 | B 2x4096 | fx ----
static constexpr int G_SOFF_B  = 2048;
static constexpr int G_SOFF_FX = 10240;
static constexpr int G_DYN_SMEM = (10240 + 768) * 4;     // 44032 B

// ---- persistent final GEMM smem (u32): B 32768 | A 16384 | fx 768 ----
static constexpr int P_SOFF_A  = 32768;
static constexpr int P_SOFF_FX = 49152;
static constexpr int P_DYN_SMEM = (49152 + 768) * 4;     // 199680 B

// ---- fused kernel smem (u32), 64-row tile ----
static constexpr int FS_ASTG = 0;                 // 2*1024
static constexpr int FS_BSTG = 2048;              // 2*4096
static constexpr int FS_VA   = 10240;             // 64*132
static constexpr int FS_Q    = 18688;             // 512
static constexpr int FS_OM   = 19200;             // 64*36 fp32
static constexpr int FS_FX   = 21504;             // floats (4352)
static constexpr int FXF_KB = 0, FXF_DMB = 256, FXF_DBB = 512, FXF_VB = 768,
                     FXF_CW = 1024, FXF_W1F = 2048, FXF_B1F = 3584,
                     FXF_DIFF = 4096;             // 256
static constexpr int FUSED_SMEM = (21504 + 4352) * 4;    // 103424 B

// ------------------------- device scratch (static) -------------------------
__device__ float g_part1[STAT_BLOCKS * 12];
__device__ float g_w1f[2][Cd * 3];
__device__ float g_b1f[2][Cd];
__device__ uint32_t g_q16[BNp * 128];
__device__ uint32_t g_we16[(size_t)R_ * 128];
__device__ float g_part2[(size_t)NTILES * 512];
__device__ float g_part2r[64 * 512];
__device__ float g_s2[Cd], g_t2[Cd];
__device__ uint32_t g_Bpk[6 * 2 * 8 * 2048];

// ----------------------------- PTX helpers ---------------------------------
__device__ __forceinline__ uint32_t smem_u32(const void* p) {
    uint32_t a;
    asm("{ .reg .u64 t; cvta.to.shared.u64 t, %1; cvt.u32.u64 %0, t; }"
        : "=r"(a) : "l"(p));
    return a;
}
__device__ __forceinline__ void cp16(uint32_t dst, const void* src) {
    asm volatile("cp.async.cg.shared.global [%0], [%1], 16;"
                 :: "r"(dst), "l"(src) : "memory");
}
__device__ __forceinline__ void cp_commit() {
    asm volatile("cp.async.commit_group;" ::: "memory");
}
template <int N>
__device__ __forceinline__ void cp_wait() {
    asm volatile("cp.async.wait_group %0;" :: "n"(N) : "memory");
}
__device__ __forceinline__ void mma_f16(float* c, const uint32_t* a,
                                        uint32_t b0, uint32_t b1) {
    asm volatile("mma.sync.aligned.m16n8k16.row.col.f32.f16.f16.f32 "
                 "{%0,%1,%2,%3}, {%4,%5,%6,%7}, {%8,%9}, {%0,%1,%2,%3};"
                 : "+f"(c[0]), "+f"(c[1]), "+f"(c[2]), "+f"(c[3])
                 : "r"(a[0]), "r"(a[1]), "r"(a[2]), "r"(a[3]),
                   "r"(b0), "r"(b1));
}
__device__ __forceinline__ uint32_t f16pk(float lo, float hi) {
    uint32_t r;
    asm("cvt.rn.f16x2.f32 %0, %1, %2;" : "=r"(r) : "f"(hi), "f"(lo));
    return r;
}
__device__ __forceinline__ float2 upk(uint32_t u) {
    float2 f;
    asm("{ .reg .b16 lo, hi; mov.b32 {lo, hi}, %2; "
        "cvt.f32.f16 %0, lo; cvt.f32.f16 %1, hi; }"
        : "=f"(f.x), "=f"(f.y) : "r"(u));
    return f;
}
__device__ __forceinline__ int pkidx(int n, int p) {
    return n * 16 + 4 * ((p & 3) ^ (n & 3)) + 2 * (p >> 3) + ((p >> 2) & 1);
}

// ------------------------------- K1: stats --------------------------------
__global__ void diffstats_kernel(const float* __restrict__ pts,
                                 const float* __restrict__ nbr) {
    float s[12];
#pragma unroll
    for (int i = 0; i < 12; i++) s[i] = 0.f;
    int tid = threadIdx.x;
    for (int r = blockIdx.x * blockDim.x + tid; r < R_; r += gridDim.x * blockDim.x) {
        int bn = r >> 4;
        float d[3];
#pragma unroll
        for (int j = 0; j < 3; j++) d[j] = pts[bn * 3 + j] - nbr[(size_t)r * 3 + j];
#pragma unroll
        for (int j = 0; j < 3; j++) s[j] += d[j];
#pragma unroll
        for (int j = 0; j < 3; j++)
#pragma unroll
            for (int k = 0; k < 3; k++) s[3 + j * 3 + k] += d[j] * d[k];
    }
    __shared__ float red[256];
    for (int comp = 0; comp < 12; comp++) {
        red[tid] = s[comp];
        __syncthreads();
        for (int off = 128; off > 0; off >>= 1) {
            if (tid < off) red[tid] += red[tid + off];
            __syncthreads();
        }
        if (tid == 0) g_part1[blockIdx.x * 12 + comp] = red[0];
        __syncthreads();
    }
}

// ------------------------------ K2: BN1 fold -------------------------------
__global__ void fold_kernel(const float* __restrict__ dm_w1, const float* __restrict__ dm_b1,
                            const float* __restrict__ dm_g,  const float* __restrict__ dm_be,
                            const float* __restrict__ db_w1, const float* __restrict__ db_b1,
                            const float* __restrict__ db_g,  const float* __restrict__ db_be) {
    __shared__ float st[12];
    __shared__ float mu[3], cov[9];
    int tid = threadIdx.x;
    if (tid < 12) {
        float a = 0.f;
        for (int b = 0; b < STAT_BLOCKS; b++) a += g_part1[b * 12 + tid];
        st[tid] = a / (float)R_;
    }
    __syncthreads();
    if (tid < 3) mu[tid] = st[tid];
    if (tid < 9) {
        int j = tid / 3, k = tid % 3;
        cov[tid] = st[3 + tid] - st[j] * st[k];
    }
    __syncthreads();
    int c = tid;
    for (int which = 0; which < 2; which++) {
        const float* w1 = which ? db_w1 : dm_w1;
        const float* b1 = which ? db_b1 : dm_b1;
        const float* gg = which ? db_g  : dm_g;
        const float* be = which ? db_be : dm_be;
        float w0 = w1[c * 3], w1v = w1[c * 3 + 1], w2v = w1[c * 3 + 2];
        float var = w0 * w0 * cov[0] + w1v * w1v * cov[4] + w2v * w2v * cov[8]
                  + 2.f * (w0 * w1v * cov[1] + w0 * w2v * cov[2] + w1v * w2v * cov[5]);
        float mdot = w0 * mu[0] + w1v * mu[1] + w2v * mu[2];
        float m = mdot + b1[c];
        float s = gg[c] * rsqrtf(var + EPSV);
        g_w1f[which][c * 3]     = w0 * s;
        g_w1f[which][c * 3 + 1] = w1v * s;
        g_w1f[which][c * 3 + 2] = w2v * s;
        g_b1f[which][c] = be[c] + s * (b1[c] - m);
    }
}

// ----------------------- weight prep: fp32 -> packed fp16 -------------------
__global__ void prep_weights(const float* __restrict__ q_w, const float* __restrict__ k_w,
                             const float* __restrict__ v_w, const float* __restrict__ dm_w2,
                             const float* __restrict__ db_w2, const float* __restrict__ lin_w) {
    int c = blockIdx.x, nb = blockIdx.y, mat = blockIdx.z;
    const float* W = mat == 0 ? q_w : mat == 1 ? k_w : mat == 2 ? v_w :
                     mat == 3 ? dm_w2 : mat == 4 ? db_w2 : lin_w;
    uint32_t* dst = g_Bpk + (((size_t)mat * 2 + nb) * 8 + c) * 2048;
    int tid = threadIdx.x;
    int n = tid >> 1, q = tid & 1;
    const float* src = W + (size_t)(nb * 128 + n) * 256 + c * 32 + q * 16;
    float cc[16];
#pragma unroll
    for (int j = 0; j < 16; j += 4) {
        float4 v = *(const float4*)&src[j];
        cc[j] = v.x; cc[j + 1] = v.y; cc[j + 2] = v.z; cc[j + 3] = v.w;
    }
#pragma unroll
    for (int t = 0; t < 4; t++)
#pragma unroll
        for (int u = 0; u < 2; u++) {
            int p = 8 * q + t + 4 * u;
            dst[pkidx(n, p)] = f16pk(cc[2 * t + 8 * u], cc[2 * t + 8 * u + 1]);
        }
}

// ----------------- standalone GEMM (q): 64-row tiles, full N ----------------
__global__ void __launch_bounds__(256, 2)
gemm_q(const float* __restrict__ A, const uint32_t* __restrict__ Bpk,
       const float* __restrict__ bias, uint32_t* __restrict__ O16) {
    extern __shared__ uint32_t sm[];
    float* bias_s = (float*)(sm + G_SOFF_FX);

    int tid = threadIdx.x;
    int rowBase = blockIdx.x * 64;
    bias_s[tid] = bias[tid];
    __syncthreads();

    uint32_t smemB_addr = smem_u32(sm + G_SOFF_B);
    auto cp_b = [&](int stage, int c) {
        uint32_t dstb = smemB_addr + (uint32_t)stage * 16384u;
#pragma unroll
        for (int i = 0; i < 4; i++) {
            int off = (tid + i * 256) * 4;
            const uint32_t* src = (off < 2048)
                ? Bpk + (size_t)c * 2048 + off
                : Bpk + (size_t)(8 + c) * 2048 + (off - 2048);
            cp16(dstb + (uint32_t)off * 4u, src);
        }
        cp_commit();
    };
    uint2 aU[2];
    auto load_a = [&](int kb) {
#pragma unroll
        for (int i = 0; i < 2; i++) {
            int f = tid + i * 256, row = f >> 3, kq = f & 7;
            float4 v = *(const float4*)&A[(size_t)(rowBase + row) * 256 + kb + kq * 4];
            aU[i].x = f16pk(v.x, v.y);
            aU[i].y = f16pk(v.z, v.w);
        }
    };
    auto sts_a = [&](int stage) {
        uint32_t* dst = sm + stage * 1024;
#pragma unroll
        for (int i = 0; i < 2; i++) {
            int f = tid + i * 256, row = f >> 3, kq = f & 7;
            dst[pkidx(row, 2 * kq)]     = aU[i].x;
            dst[pkidx(row, 2 * kq + 1)] = aU[i].y;
        }
    };

    cp_b(0, 0);
    cp_b(1, 1);
    load_a(0);
    sts_a(0);
    cp_wait<0>();
    __syncthreads();

    int lane = tid & 31, w = tid >> 5;
    int la3 = lane & 3, lg = lane >> 2;
    int axor = 4 * (la3 ^ (lg & 3));
    const int aOff = lg * 16 + axor;
    const int bOff = (w * 32 + lg) * 16 + axor;

    float acc[4][4][4];
#pragma unroll
    for (int mt = 0; mt < 4; mt++)
#pragma unroll
        for (int nt = 0; nt < 4; nt++)
#pragma unroll
            for (int r = 0; r < 4; r++) acc[mt][nt][r] = 0.f;

    for (int c = 0; c < 8; c++) {
        int st = c & 1;
        const uint32_t* As = sm + st * 1024;
        const uint32_t* Bs = sm + G_SOFF_B + st * 4096;

        uint4 Vb[4];
#pragma unroll
        for (int nt = 0; nt < 4; nt++)
            Vb[nt] = *(const uint4*)&Bs[bOff + nt * 128];
#pragma unroll
        for (int mt = 0; mt < 2; mt++) {
            uint4 U0 = *(const uint4*)&As[aOff + mt * 256];
            uint4 U1 = *(const uint4*)&As[aOff + mt * 256 + 128];
            uint32_t a0[4] = {U0.x, U1.x, U0.y, U1.y};
            uint32_t a1[4] = {U0.z, U1.z, U0.w, U1.w};
#pragma unroll
            for (int nt = 0; nt < 4; nt++)
                mma_f16(acc[mt][nt], a0, Vb[nt].x, Vb[nt].y);
#pragma unroll
            for (int nt = 0; nt < 4; nt++)
                mma_f16(acc[mt][nt], a1, Vb[nt].z, Vb[nt].w);
        }
        if (c < 7) load_a((c + 1) * 32);
#pragma unroll
        for (int mt = 2; mt < 4; mt++) {
            uint4 U0 = *(const uint4*)&As[aOff + mt * 256];
            uint4 U1 = *(const uint4*)&As[aOff + mt * 256 + 128];
            uint32_t a0[4] = {U0.x, U1.x, U0.y, U1.y};
            uint32_t a1[4] = {U0.z, U1.z, U0.w, U1.w};
#pragma unroll
            for (int nt = 0; nt < 4; nt++)
                mma_f16(acc[mt][nt], a0, Vb[nt].x, Vb[nt].y);
#pragma unroll
            for (int nt = 0; nt < 4; nt++)
                mma_f16(acc[mt][nt], a1, Vb[nt].z, Vb[nt].w);
        }
        if (c < 7) sts_a(st ^ 1);
        cp_wait<0>();
        __syncthreads();
        if (c + 2 < 8) cp_b(st, c + 2);
    }

#pragma unroll
    for (int mt = 0; mt < 4; mt++) {
        int row0 = rowBase + mt * 16 + lg;
#pragma unroll
        for (int nt = 0; nt < 4; nt++) {
            int col = w * 32 + nt * 8 + 2 * la3;
            float b0 = bias_s[col], b1 = bias_s[col + 1];
            O16[(size_t)row0 * 128 + (col >> 1)] =
                f16pk(acc[mt][nt][0] + b0, acc[mt][nt][1] + b1);
            O16[(size_t)(row0 + 8) * 128 + (col >> 1)] =
                f16pk(acc[mt][nt][2] + b0, acc[mt][nt][3] + b1);
        }
    }
}

// --------------- persistent weight-stationary FINAL GEMM --------------------
__global__ void __launch_bounds__(512, 1)
gemm_final(const uint32_t* __restrict__ A16, const uint32_t* __restrict__ Bpk,
           const float* __restrict__ bias, float* __restrict__ Out) {
    extern __shared__ uint32_t sm[];
    float* fx = (float*)(sm + P_SOFF_FX);
    float* bias_s = fx;
    float* s2_s   = fx + 256;
    float* t2_s   = fx + 512;
    int tid = threadIdx.x;
    if (tid < 256) {
        bias_s[tid] = bias[tid];
        s2_s[tid]   = g_s2[tid];
        t2_s[tid]   = g_t2[tid];
    }
    uint32_t smemB = smem_u32(sm);
#pragma unroll
    for (int i = 0; i < 16; i++) {
        int o = (tid + i * 512) * 4;
        int c = o >> 12, within = o & 4095;
        int nb = within >> 11, idx = within & 2047;
        cp16(smemB + (uint32_t)o * 4u,
             Bpk + (size_t)(nb * 8 + c) * 2048 + idx);
    }
    cp_commit();
    cp_wait<0>();
    __syncthreads();

    int lane = tid & 31, w = tid >> 5;
    int wm = w & 1, wn = w >> 1;
    int la3 = lane & 3, lg = lane >> 2;
    int axor = 4 * (la3 ^ (lg & 3));
    const int bOff = (wn * 32 + lg) * 16 + axor;
    const int aOff = (wm * 64 + lg) * 16 + axor;

    for (int t = blockIdx.x; t < R_ / 128; t += gridDim.x) {
        int rowBase = t * 128;
#pragma unroll
        for (int i = 0; i < 16; i++) {
            int f = tid + i * 512;
            int c = f >> 10, r = f & 1023, row = r >> 3, kq = r & 7;
            uint2 u = *(const uint2*)&A16[(size_t)(rowBase + row) * 128 + c * 16 + kq * 2];
            float2 f0 = upk(u.x), f1 = upk(u.y);
            int k = c * 32 + kq * 4;
            float x0 = fmaxf(fmaf(f0.x, s2_s[k],     t2_s[k]),     0.f);
            float x1 = fmaxf(fmaf(f0.y, s2_s[k + 1], t2_s[k + 1]), 0.f);
            float x2 = fmaxf(fmaf(f1.x, s2_s[k + 2], t2_s[k + 2]), 0.f);
            float x3 = fmaxf(fmaf(f1.y, s2_s[k + 3], t2_s[k + 3]), 0.f);
            uint32_t* dst = sm + P_SOFF_A + c * 2048;
            dst[pkidx(row, 2 * kq)]     = f16pk(x0, x1);
            dst[pkidx(row, 2 * kq + 1)] = f16pk(x2, x3);
        }
        __syncthreads();

        float acc[4][4][4];
#pragma unroll
        for (int mt = 0; mt < 4; mt++)
#pragma unroll
            for (int nt = 0; nt < 4; nt++)
#pragma unroll
                for (int r = 0; r < 4; r++) acc[mt][nt][r] = 0.f;

#pragma unroll
        for (int c = 0; c < 8; c++) {
            const uint32_t* As = sm + P_SOFF_A + c * 2048;
            const uint32_t* Bs = sm + c * 4096;
            uint4 Vb[4];
#pragma unroll
            for (int nt = 0; nt < 4; nt++)
                Vb[nt] = *(const uint4*)&Bs[bOff + nt * 128];
#pragma unroll
            for (int mt = 0; mt < 4; mt++) {
                uint4 U0 = *(const uint4*)&As[aOff + mt * 256];
                uint4 U1 = *(const uint4*)&As[aOff + mt * 256 + 128];
                uint32_t a0[4] = {U0.x, U1.x, U0.y, U1.y};
                uint32_t a1[4] = {U0.z, U1.z, U0.w, U1.w};
#pragma unroll
                for (int nt = 0; nt < 4; nt++)
                    mma_f16(acc[mt][nt], a0, Vb[nt].x, Vb[nt].y);
#pragma unroll
                for (int nt = 0; nt < 4; nt++)
                    mma_f16(acc[mt][nt], a1, Vb[nt].z, Vb[nt].w);
            }
        }
        __syncthreads();

#pragma unroll
        for (int mt = 0; mt < 4; mt++) {
            int row0 = rowBase + wm * 64 + mt * 16 + lg;
#pragma unroll
            for (int nt = 0; nt < 4; nt++) {
                int col = wn * 32 + nt * 8 + 2 * la3;
                float b0 = bias_s[col], b1 = bias_s[col + 1];
                *(float2*)&Out[(size_t)row0 * 256 + col] =
                    make_float2(acc[mt][nt][0] + b0, acc[mt][nt][1] + b1);
                *(float2*)&Out[(size_t)(row0 + 8) * 256 + col] =
                    make_float2(acc[mt][nt][2] + b0, acc[mt][nt][3] + b1);
            }
        }
    }
}

// ----------------------- fused produce+attention subpass --------------------
// EPI: 0 = qk = q-k ; 1 = va = dm*qk ; 2 = va += db ; 3 = we = omega*v
// nextBmat: prefetch target issued after mainloop (before epilogue).
// pf: B chunks 0/1 already in flight from previous subpass's prefetch.
template <int EPI, bool POS>
__device__ __noinline__ void run_subpass(
    uint32_t* sm, int tid, int rowBase,
    const float* __restrict__ nf,
    const uint32_t* __restrict__ Bmat,
    const uint32_t* __restrict__ nextBmat, bool pf,
    const float* bias_s, const float* w1f_s, const float* b1f_s,
    const float* diff_s, int blockId) {

    uint32_t smemB_addr = smem_u32(sm + FS_BSTG);
    auto cp_b = [&](int stage, int c, const uint32_t* M) {
        uint32_t dstb = smemB_addr + (uint32_t)stage * 16384u;
#pragma unroll
        for (int i = 0; i < 4; i++) {
            int off = (tid + i * 256) * 4;
            const uint32_t* src = (off < 2048)
                ? M + (size_t)c * 2048 + off
                : M + (size_t)(8 + c) * 2048 + (off - 2048);
            cp16(dstb + (uint32_t)off * 4u, src);
        }
        cp_commit();
    };

    uint2 aU[2];
    auto load_a = [&](int kb) {
#pragma unroll
        for (int i = 0; i < 2; i++) {
            int f = tid + i * 256, row = f >> 3, kq = f & 7;
            if (POS) {
                float d0 = diff_s[row * 4], d1 = diff_s[row * 4 + 1],
                      d2 = diff_s[row * 4 + 2];
                float t[4];
#pragma unroll
                for (int j = 0; j < 4; j++) {
                    int k = kb + kq * 4 + j;
                    float h = fmaf(d0, w1f_s[k * 3],
                              fmaf(d1, w1f_s[k * 3 + 1],
                              fmaf(d2, w1f_s[k * 3 + 2], b1f_s[k])));
                    t[j] = fmaxf(h, 0.f);
                }
                aU[i].x = f16pk(t[0], t[1]);
                aU[i].y = f16pk(t[2], t[3]);
            } else {
                float4 v = *(const float4*)&nf[(size_t)(rowBase + row) * 256 + kb + kq * 4];
                aU[i].x = f16pk(v.x, v.y);
                aU[i].y = f16pk(v.z, v.w);
            }
        }
    };
    auto sts_a = [&](int stage) {
        uint32_t* dst = sm + FS_ASTG + stage * 1024;
#pragma unroll
        for (int i = 0; i < 2; i++) {
            int f = tid + i * 256, row = f >> 3, kq = f & 7;
            dst[pkidx(row, 2 * kq)]     = aU[i].x;
            dst[pkidx(row, 2 * kq + 1)] = aU[i].y;
        }
    };

    if (!pf) {
        cp_b(0, 0, Bmat);
        cp_b(1, 1, Bmat);
    }
    load_a(0);
    sts_a(0);
    cp_wait<0>();
    __syncthreads();

    int lane = tid & 31, w = tid >> 5;
    int la3 = lane & 3, lg = lane >> 2;
    int axor = 4 * (la3 ^ (lg & 3));
    const int aOff = lg * 16 + axor;
    const int bOff = (w * 32 + lg) * 16 + axor;

    float acc[4][4][4];
#pragma unroll
    for (int mt = 0; mt < 4; mt++)
#pragma unroll
        for (int nt = 0; nt < 4; nt++)
#pragma unroll
            for (int r = 0; r < 4; r++) acc[mt][nt][r] = 0.f;

    for (int c = 0; c < 8; c++) {
        int st = c & 1;
        const uint32_t* As = sm + FS_ASTG + st * 1024;
        const uint32_t* Bs = sm + FS_BSTG + st * 4096;

        uint4 Vb[4];
#pragma unroll
        for (int nt = 0; nt < 4; nt++)
            Vb[nt] = *(const uint4*)&Bs[bOff + nt * 128];
#pragma unroll
        for (int mt = 0; mt < 2; mt++) {
            uint4 U0 = *(const uint4*)&As[aOff + mt * 256];
            uint4 U1 = *(const uint4*)&As[aOff + mt * 256 + 128];
            uint32_t a0[4] = {U0.x, U1.x, U0.y, U1.y};
            uint32_t a1[4] = {U0.z, U1.z, U0.w, U1.w};
#pragma unroll
            for (int nt = 0; nt < 4; nt++)
                mma_f16(acc[mt][nt], a0, Vb[nt].x, Vb[nt].y);
#pragma unroll
            for (int nt = 0; nt < 4; nt++)
                mma_f16(acc[mt][nt], a1, Vb[nt].z, Vb[nt].w);
        }
        if (c < 7) load_a((c + 1) * 32);
#pragma unroll
        for (int mt = 2; mt < 4; mt++) {
            uint4 U0 = *(const uint4*)&As[aOff + mt * 256];
            uint4 U1 = *(const uint4*)&As[aOff + mt * 256 + 128];
            uint32_t a0[4] = {U0.x, U1.x, U0.y, U1.y};
            uint32_t a1[4] = {U0.z, U1.z, U0.w, U1.w};
#pragma unroll
            for (int nt = 0; nt < 4; nt++)
                mma_f16(acc[mt][nt], a0, Vb[nt].x, Vb[nt].y);
#pragma unroll
            for (int nt = 0; nt < 4; nt++)
                mma_f16(acc[mt][nt], a1, Vb[nt].z, Vb[nt].w);
        }
        if (c < 7) sts_a(st ^ 1);
        cp_wait<0>();
        __syncthreads();
        if (c + 2 < 8) cp_b(st, c + 2, Bmat);
    }

    // ---- prefetch next subpass's first B chunks (both stages drained) ----
    if (nextBmat) {
        cp_b(0, 0, nextBmat);
        cp_b(1, 1, nextBmat);
    }

    // ---- epilogue ----
    float csum[8], csq[8];
#pragma unroll
    for (int j = 0; j < 8; j++) { csum[j] = 0.f; csq[j] = 0.f; }

#pragma unroll
    for (int mt = 0; mt < 4; mt++) {
        int row0 = mt * 16 + lg;
#pragma unroll
        for (int nt = 0; nt < 4; nt++) {
            int col = w * 32 + nt * 8 + 2 * la3;
            float b0 = bias_s[col], b1 = bias_s[col + 1];
            int vi0 = row0 * 132 + (col >> 1);
            int vi1 = (row0 + 8) * 132 + (col >> 1);
            float a0 = acc[mt][nt][0] + b0, a1 = acc[mt][nt][1] + b1;
            float a2 = acc[mt][nt][2] + b0, a3 = acc[mt][nt][3] + b1;
            if (EPI == 0) {
                float2 qv = upk(sm[FS_Q + mt * 128 + (col >> 1)]);
                sm[FS_VA + vi0] = f16pk(qv.x - a0, qv.y - a1);
                sm[FS_VA + vi1] = f16pk(qv.x - a2, qv.y - a3);
            } else if (EPI == 1) {
                float2 u0 = upk(sm[FS_VA + vi0]), u1 = upk(sm[FS_VA + vi1]);
                sm[FS_VA + vi0] = f16pk(a0 * u0.x, a1 * u0.y);
                sm[FS_VA + vi1] = f16pk(a2 * u1.x, a3 * u1.y);
            } else if (EPI == 2) {
                float2 u0 = upk(sm[FS_VA + vi0]), u1 = upk(sm[FS_VA + vi1]);
                sm[FS_VA + vi0] = f16pk(u0.x + a0, u0.y + a1);
                sm[FS_VA + vi1] = f16pk(u1.x + a2, u1.y + a3);
            } else {
                const float* om = (const float*)(sm + FS_OM);
                float o0 = om[row0 * 36 + (col >> 3)];
                float o1 = om[(row0 + 8) * 36 + (col >> 3)];
                float w00 = o0 * a0, w01 = o0 * a1;
                float w10 = o1 * a2, w11 = o1 * a3;
                g_we16[(size_t)(rowBase + row0) * 128 + (col >> 1)]     = f16pk(w00, w01);
                g_we16[(size_t)(rowBase + row0 + 8) * 128 + (col >> 1)] = f16pk(w10, w11);
                csum[nt * 2]     += w00 + w10;
                csum[nt * 2 + 1] += w01 + w11;
                csq[nt * 2]      += w00 * w00 + w10 * w10;
                csq[nt * 2 + 1]  += w01 * w01 + w11 * w11;
            }
        }
    }
    if (EPI == 3) {
#pragma unroll
        for (int j = 0; j < 8; j++) {
#pragma unroll
            for (int off = 4; off < 32; off <<= 1) {
                csum[j] += __shfl_xor_sync(0xffffffffu, csum[j], off);
                csq[j]  += __shfl_xor_sync(0xffffffffu, csq[j],  off);
            }
        }
        if (lg == 0) {
#pragma unroll
            for (int u = 0; u < 8; u++) {
                int nt = u >> 1, uu = u & 1;
                int col = w * 32 + nt * 8 + 2 * la3 + uu;
                g_part2[(size_t)blockId * 512 + col]       = csum[u];
                g_part2[(size_t)blockId * 512 + 256 + col] = csq[u];
            }
        }
        __syncthreads();
    } else {
        __syncthreads();
    }
}

// ------------------- persistent fused kernel (296 CTAs) ---------------------
__global__ void __launch_bounds__(256, 2)
fused_kernel(const float* __restrict__ nf, const float* __restrict__ pts,
             const float* __restrict__ nbr,
             const float* __restrict__ k_b, const float* __restrict__ dm_b2,
             const float* __restrict__ db_b2, const float* __restrict__ v_b,
             const float* __restrict__ convw) {
    extern __shared__ uint32_t sm[];
    float* fx = (float*)(sm + FS_FX);
    int tid = threadIdx.x;

    // constants: once per CTA
    fx[FXF_KB + tid]  = k_b[tid];
    fx[FXF_DMB + tid] = dm_b2[tid];
    fx[FXF_DBB + tid] = db_b2[tid];
    fx[FXF_VB + tid]  = v_b[tid];
    fx[FXF_B1F + tid]       = g_b1f[0][tid];
    fx[FXF_B1F + 256 + tid] = g_b1f[1][tid];
    for (int i = tid; i < 1024; i += 256) fx[FXF_CW + i] = convw[i];
    for (int i = tid; i < 768; i += 256) {
        fx[FXF_W1F + i]       = g_w1f[0][i];
        fx[FXF_W1F + 768 + i] = g_w1f[1][i];
    }

    const uint32_t* BK  = g_Bpk + 1 * 32768;
    const uint32_t* BV  = g_Bpk + 2 * 32768;
    const uint32_t* BDM = g_Bpk + 3 * 32768;
    const uint32_t* BDB = g_Bpk + 4 * 32768;
    const float* diff_s = fx + FXF_DIFF;

    bool pf = false;
    for (int t = blockIdx.x; t < NTILES; t += gridDim.x) {
        int rowBase = t * 64;
        if (tid < 64) {
            int r = rowBase + tid, bn = r >> 4;
            fx[FXF_DIFF + tid * 4 + 0] = pts[bn * 3 + 0] - nbr[(size_t)r * 3 + 0];
            fx[FXF_DIFF + tid * 4 + 1] = pts[bn * 3 + 1] - nbr[(size_t)r * 3 + 1];
            fx[FXF_DIFF + tid * 4 + 2] = pts[bn * 3 + 2] - nbr[(size_t)r * 3 + 2];
        }
        {
            int bnb = rowBase >> 4;
            for (int i = tid; i < 512; i += 256)
                sm[FS_Q + i] = g_q16[bnb * 128 + i];
        }
        __syncthreads();

        run_subpass<0, false>(sm, tid, rowBase, nf, BK, BDM, pf,
                              fx + FXF_KB, nullptr, nullptr, diff_s, t);
        run_subpass<1, true >(sm, tid, rowBase, nf, BDM, BDB, true,
                              fx + FXF_DMB, fx + FXF_W1F, fx + FXF_B1F, diff_s, t);
        run_subpass<2, true >(sm, tid, rowBase, nf, BDB, BV, true,
                              fx + FXF_DBB, fx + FXF_W1F + 768, fx + FXF_B1F + 256,
                              diff_s, t);

        // ---- attention: va -> omega ----
        __syncthreads();
        {
            int l = tid & 31, w = tid >> 5;
            float cwr[32];
#pragma unroll
            for (int i = 0; i < 32; i++)
                cwr[i] = fx[FXF_CW + (l >> 2) * 128 + (l & 3) * 32 + i];
            float* om = (float*)(sm + FS_OM);
            int gb = (l >> 2) * 16;
            for (int it = 0; it < 8; it++) {
                int row = w * 8 + it;
                const uint32_t* vrow = sm + FS_VA + row * 132;
                float acc = 0.f;
#pragma unroll
                for (int tt = 0; tt < 16; tt += 2) {
                    uint2 u = *(const uint2*)&vrow[gb + tt];
                    float2 f0 = upk(u.x), f1 = upk(u.y);
                    int i0 = tt * 2;
                    acc = fmaf(f0.x, cwr[i0], acc);
                    acc = fmaf(f0.y, cwr[i0 + 1], acc);
                    acc = fmaf(f1.x, cwr[i0 + 2], acc);
                    acc = fmaf(f1.y, cwr[i0 + 3], acc);
                }
                float mx = acc;
#pragma unroll
                for (int off = 16; off > 0; off >>= 1)
                    mx = fmaxf(mx, __shfl_xor_sync(0xffffffffu, mx, off));
                float e = expf(acc - mx);
                float ss = e;
#pragma unroll
                for (int off = 16; off > 0; off >>= 1)
                    ss += __shfl_xor_sync(0xffffffffu, ss, off);
                om[row * 36 + l] = e / ss;
            }
        }
        __syncthreads();

        const uint32_t* nxt = (t + gridDim.x < NTILES) ? BK : nullptr;
        run_subpass<3, false>(sm, tid, rowBase, nf, BV, nxt, true,
                              fx + FXF_VB, nullptr, nullptr, diff_s, t);
        pf = true;
    }
}

// --------------------------- BN2 reductions --------------------------------
__global__ void reduce_part2() {
    int b = blockIdx.x, tid = threadIdx.x;
    for (int c = tid; c < 512; c += 256) {
        float s = 0.f;
#pragma unroll 8
        for (int i = 0; i < 64; i++)
            s += g_part2[(size_t)(b * 64 + i) * 512 + c];
        g_part2r[b * 512 + c] = s;
    }
}

__global__ void finalize2_kernel(const float* __restrict__ bn_g,
                                 const float* __restrict__ bn_b) {
    int c = threadIdx.x;
    float s = 0.f, sq = 0.f;
    for (int b = 0; b < 64; b++) {
        s  += g_part2r[b * 512 + c];
        sq += g_part2r[b * 512 + 256 + c];
    }
    float mean = s / (float)R_;
    float var = sq / (float)R_ - mean * mean;
    float sc = bn_g[c] * rsqrtf(var + EPSV);
    g_s2[c] = sc;
    g_t2[c] = bn_b[c] - mean * sc;
}

// ------------------------------- launch -------------------------------------
extern "C" void kernel_launch(void* const* d_in, const int* in_sizes, int n_in,
                              void* d_out, int out_size) {
    const float* pts   = (const float*)d_in[0];
    const float* pf    = (const float*)d_in[1];
    const float* nbr   = (const float*)d_in[2];
    const float* nf    = (const float*)d_in[3];
    const float* dm_w1 = (const float*)d_in[4];
    const float* dm_b1 = (const float*)d_in[5];
    const float* dm_w2 = (const float*)d_in[6];
    const float* dm_b2 = (const float*)d_in[7];
    const float* dm_g  = (const float*)d_in[8];
    const float* dm_be = (const float*)d_in[9];
    const float* db_w1 = (const float*)d_in[10];
    const float* db_b1 = (const float*)d_in[11];
    const float* db_w2 = (const float*)d_in[12];
    const float* db_b2 = (const float*)d_in[13];
    const float* db_g  = (const float*)d_in[14];
    const float* db_be = (const float*)d_in[15];
    const float* q_w   = (const float*)d_in[16];
    const float* q_b   = (const float*)d_in[17];
    const float* k_w   = (const float*)d_in[18];
    const float* k_b   = (const float*)d_in[19];
    const float* v_w   = (const float*)d_in[20];
    const float* v_b   = (const float*)d_in[21];
    const float* convw = (const float*)d_in[22];
    const float* bn_g  = (const float*)d_in[23];
    const float* bn_b  = (const float*)d_in[24];
    const float* lin_w = (const float*)d_in[25];
    const float* lin_b = (const float*)d_in[26];
    float* out = (float*)d_out;

    void *p_q, *p_we, *p_bpk;
    cudaGetSymbolAddress(&p_q,   g_q16);
    cudaGetSymbolAddress(&p_we,  g_we16);
    cudaGetSymbolAddress(&p_bpk, g_Bpk);
    const uint32_t* Bpk = (const uint32_t*)p_bpk;

    cudaFuncSetAttribute(gemm_q,
                         cudaFuncAttributeMaxDynamicSharedMemorySize, G_DYN_SMEM);
    cudaFuncSetAttribute(gemm_final,
                         cudaFuncAttributeMaxDynamicSharedMemorySize, P_DYN_SMEM);
    cudaFuncSetAttribute(fused_kernel,
                         cudaFuncAttributeMaxDynamicSharedMemorySize, FUSED_SMEM);

    prep_weights<<<dim3(8, 2, 6), 256>>>(q_w, k_w, v_w, dm_w2, db_w2, lin_w);
    diffstats_kernel<<<STAT_BLOCKS, 256>>>(pts, nbr);
    fold_kernel<<<1, 256>>>(dm_w1, dm_b1, dm_g, dm_be, db_w1, db_b1, db_g, db_be);

    gemm_q<<<BNp / 64, 256, G_DYN_SMEM>>>(pf, Bpk + 0 * 32768, q_b,
                                          (uint32_t*)p_q);

    fused_kernel<<<FGRID, 256, FUSED_SMEM>>>(nf, pts, nbr,
                                             k_b, dm_b2, db_b2, v_b, convw);

    reduce_part2<<<64, 256>>>();
    finalize2_kernel<<<1, 256>>>(bn_g, bn_b);

    gemm_final<<<PGRID, 512, P_DYN_SMEM>>>((const uint32_t*)p_we,
                                           Bpk + 5 * 32768, lin_b, out);
}

// round 15
// speedup vs baseline: 1.0670x; 1.0670x over previous
#include <cuda_runtime.h>
#include <cstdint>

// ---------------------------------------------------------------------------
// GroupVectorAttention — best-known configuration (R11, 816us):
// fused produce+attention (64-row tiles, occ 2, 4096 CTAs) + persistent
// weight-stationary final GEMM + 64-row q-GEMM. fp16 HMMA throughout,
// analytic BN1 folding, deterministic BN2 partials. Reverted after R12-R14
// variants all regressed.
// ---------------------------------------------------------------------------

#define EPSV 1e-5f

static constexpr int Bb = 4, Nn = 4096, Mm = 16, Cd = 256;
static constexpr int R_ = Bb * Nn * Mm;       // 262144
static constexpr int BNp = Bb * Nn;           // 16384
static constexpr int STAT_BLOCKS = 256;
static constexpr int NTILES = R_ / 64;        // 4096 fused tiles
static constexpr int PGRID = 148;

// ---- standalone GEMM smem (u32): A 2x1024 | B 2x4096 | fx ----
static constexpr int G_SOFF_B  = 2048;
static constexpr int G_SOFF_FX = 10240;
static constexpr int G_DYN_SMEM = (10240 + 768) * 4;     // 44032 B

// ---- persistent final GEMM smem (u32): B 32768 | A 16384 | fx 768 ----
static constexpr int P_SOFF_A  = 32768;
static constexpr int P_SOFF_FX = 49152;
static constexpr int P_DYN_SMEM = (49152 + 768) * 4;     // 199680 B

// ---- fused kernel smem (u32), 64-row tile ----
static constexpr int FS_ASTG = 0;                 // 2*1024
static constexpr int FS_BSTG = 2048;              // 2*4096
static constexpr int FS_VA   = 10240;             // 64*132
static constexpr int FS_Q    = 18688;             // 512
static constexpr int FS_OM   = 19200;             // 64*36 fp32
static constexpr int FS_FX   = 21504;             // floats (4352)
static constexpr int FXF_KB = 0, FXF_DMB = 256, FXF_DBB = 512, FXF_VB = 768,
                     FXF_CW = 1024, FXF_W1F = 2048, FXF_B1F = 3584,
                     FXF_DIFF = 4096;             // 256
static constexpr int FUSED_SMEM = (21504 + 4352) * 4;    // 103424 B

// ------------------------- device scratch (static) -------------------------
__device__ float g_part1[STAT_BLOCKS * 12];
__device__ float g_w1f[2][Cd * 3];
__device__ float g_b1f[2][Cd];
__device__ uint32_t g_q16[BNp * 128];
__device__ uint32_t g_we16[(size_t)R_ * 128];
__device__ float g_part2[(size_t)NTILES * 512];
__device__ float g_part2r[64 * 512];
__device__ float g_s2[Cd], g_t2[Cd];
__device__ uint32_t g_Bpk[6 * 2 * 8 * 2048];

// ----------------------------- PTX helpers ---------------------------------
__device__ __forceinline__ uint32_t smem_u32(const void* p) {
    uint32_t a;
    asm("{ .reg .u64 t; cvta.to.shared.u64 t, %1; cvt.u32.u64 %0, t; }"
        : "=r"(a) : "l"(p));
    return a;
}
__device__ __forceinline__ void cp16(uint32_t dst, const void* src) {
    asm volatile("cp.async.cg.shared.global [%0], [%1], 16;"
                 :: "r"(dst), "l"(src) : "memory");
}
__device__ __forceinline__ void cp_commit() {
    asm volatile("cp.async.commit_group;" ::: "memory");
}
template <int N>
__device__ __forceinline__ void cp_wait() {
    asm volatile("cp.async.wait_group %0;" :: "n"(N) : "memory");
}
__device__ __forceinline__ void mma_f16(float* c, const uint32_t* a,
                                        uint32_t b0, uint32_t b1) {
    asm volatile("mma.sync.aligned.m16n8k16.row.col.f32.f16.f16.f32 "
                 "{%0,%1,%2,%3}, {%4,%5,%6,%7}, {%8,%9}, {%0,%1,%2,%3};"
                 : "+f"(c[0]), "+f"(c[1]), "+f"(c[2]), "+f"(c[3])
                 : "r"(a[0]), "r"(a[1]), "r"(a[2]), "r"(a[3]),
                   "r"(b0), "r"(b1));
}
__device__ __forceinline__ uint32_t f16pk(float lo, float hi) {
    uint32_t r;
    asm("cvt.rn.f16x2.f32 %0, %1, %2;" : "=r"(r) : "f"(hi), "f"(lo));
    return r;
}
__device__ __forceinline__ float2 upk(uint32_t u) {
    float2 f;
    asm("{ .reg .b16 lo, hi; mov.b32 {lo, hi}, %2; "
        "cvt.f32.f16 %0, lo; cvt.f32.f16 %1, hi; }"
        : "=f"(f.x), "=f"(f.y) : "r"(u));
    return f;
}
__device__ __forceinline__ int pkidx(int n, int p) {
    return n * 16 + 4 * ((p & 3) ^ (n & 3)) + 2 * (p >> 3) + ((p >> 2) & 1);
}

// ------------------------------- K1: stats --------------------------------
__global__ void diffstats_kernel(const float* __restrict__ pts,
                                 const float* __restrict__ nbr) {
    float s[12];
#pragma unroll
    for (int i = 0; i < 12; i++) s[i] = 0.f;
    int tid = threadIdx.x;
    for (int r = blockIdx.x * blockDim.x + tid; r < R_; r += gridDim.x * blockDim.x) {
        int bn = r >> 4;
        float d[3];
#pragma unroll
        for (int j = 0; j < 3; j++) d[j] = pts[bn * 3 + j] - nbr[(size_t)r * 3 + j];
#pragma unroll
        for (int j = 0; j < 3; j++) s[j] += d[j];
#pragma unroll
        for (int j = 0; j < 3; j++)
#pragma unroll
            for (int k = 0; k < 3; k++) s[3 + j * 3 + k] += d[j] * d[k];
    }
    __shared__ float red[256];
    for (int comp = 0; comp < 12; comp++) {
        red[tid] = s[comp];
        __syncthreads();
        for (int off = 128; off > 0; off >>= 1) {
            if (tid < off) red[tid] += red[tid + off];
            __syncthreads();
        }
        if (tid == 0) g_part1[blockIdx.x * 12 + comp] = red[0];
        __syncthreads();
    }
}

// ------------------------------ K2: BN1 fold -------------------------------
__global__ void fold_kernel(const float* __restrict__ dm_w1, const float* __restrict__ dm_b1,
                            const float* __restrict__ dm_g,  const float* __restrict__ dm_be,
                            const float* __restrict__ db_w1, const float* __restrict__ db_b1,
                            const float* __restrict__ db_g,  const float* __restrict__ db_be) {
    __shared__ float st[12];
    __shared__ float mu[3], cov[9];
    int tid = threadIdx.x;
    if (tid < 12) {
        float a = 0.f;
        for (int b = 0; b < STAT_BLOCKS; b++) a += g_part1[b * 12 + tid];
        st[tid] = a / (float)R_;
    }
    __syncthreads();
    if (tid < 3) mu[tid] = st[tid];
    if (tid < 9) {
        int j = tid / 3, k = tid % 3;
        cov[tid] = st[3 + tid] - st[j] * st[k];
    }
    __syncthreads();
    int c = tid;
    for (int which = 0; which < 2; which++) {
        const float* w1 = which ? db_w1 : dm_w1;
        const float* b1 = which ? db_b1 : dm_b1;
        const float* gg = which ? db_g  : dm_g;
        const float* be = which ? db_be : dm_be;
        float w0 = w1[c * 3], w1v = w1[c * 3 + 1], w2v = w1[c * 3 + 2];
        float var = w0 * w0 * cov[0] + w1v * w1v * cov[4] + w2v * w2v * cov[8]
                  + 2.f * (w0 * w1v * cov[1] + w0 * w2v * cov[2] + w1v * w2v * cov[5]);
        float mdot = w0 * mu[0] + w1v * mu[1] + w2v * mu[2];
        float m = mdot + b1[c];
        float s = gg[c] * rsqrtf(var + EPSV);
        g_w1f[which][c * 3]     = w0 * s;
        g_w1f[which][c * 3 + 1] = w1v * s;
        g_w1f[which][c * 3 + 2] = w2v * s;
        g_b1f[which][c] = be[c] + s * (b1[c] - m);
    }
}

// ----------------------- weight prep: fp32 -> packed fp16 -------------------
__global__ void prep_weights(const float* __restrict__ q_w, const float* __restrict__ k_w,
                             const float* __restrict__ v_w, const float* __restrict__ dm_w2,
                             const float* __restrict__ db_w2, const float* __restrict__ lin_w) {
    int c = blockIdx.x, nb = blockIdx.y, mat = blockIdx.z;
    const float* W = mat == 0 ? q_w : mat == 1 ? k_w : mat == 2 ? v_w :
                     mat == 3 ? dm_w2 : mat == 4 ? db_w2 : lin_w;
    uint32_t* dst = g_Bpk + (((size_t)mat * 2 + nb) * 8 + c) * 2048;
    int tid = threadIdx.x;
    int n = tid >> 1, q = tid & 1;
    const float* src = W + (size_t)(nb * 128 + n) * 256 + c * 32 + q * 16;
    float cc[16];
#pragma unroll
    for (int j = 0; j < 16; j += 4) {
        float4 v = *(const float4*)&src[j];
        cc[j] = v.x; cc[j + 1] = v.y; cc[j + 2] = v.z; cc[j + 3] = v.w;
    }
#pragma unroll
    for (int t = 0; t < 4; t++)
#pragma unroll
        for (int u = 0; u < 2; u++) {
            int p = 8 * q + t + 4 * u;
            dst[pkidx(n, p)] = f16pk(cc[2 * t + 8 * u], cc[2 * t + 8 * u + 1]);
        }
}

// ----------------- standalone GEMM (q): 64-row tiles, full N ----------------
__global__ void __launch_bounds__(256, 2)
gemm_q(const float* __restrict__ A, const uint32_t* __restrict__ Bpk,
       const float* __restrict__ bias, uint32_t* __restrict__ O16) {
    extern __shared__ uint32_t sm[];
    float* bias_s = (float*)(sm + G_SOFF_FX);

    int tid = threadIdx.x;
    int rowBase = blockIdx.x * 64;
    bias_s[tid] = bias[tid];
    __syncthreads();

    uint32_t smemB_addr = smem_u32(sm + G_SOFF_B);
    auto cp_b = [&](int stage, int c) {
        uint32_t dstb = smemB_addr + (uint32_t)stage * 16384u;
#pragma unroll
        for (int i = 0; i < 4; i++) {
            int off = (tid + i * 256) * 4;
            const uint32_t* src = (off < 2048)
                ? Bpk + (size_t)c * 2048 + off
                : Bpk + (size_t)(8 + c) * 2048 + (off - 2048);
            cp16(dstb + (uint32_t)off * 4u, src);
        }
        cp_commit();
    };
    uint2 aU[2];
    auto load_a = [&](int kb) {
#pragma unroll
        for (int i = 0; i < 2; i++) {
            int f = tid + i * 256, row = f >> 3, kq = f & 7;
            float4 v = *(const float4*)&A[(size_t)(rowBase + row) * 256 + kb + kq * 4];
            aU[i].x = f16pk(v.x, v.y);
            aU[i].y = f16pk(v.z, v.w);
        }
    };
    auto sts_a = [&](int stage) {
        uint32_t* dst = sm + stage * 1024;
#pragma unroll
        for (int i = 0; i < 2; i++) {
            int f = tid + i * 256, row = f >> 3, kq = f & 7;
            dst[pkidx(row, 2 * kq)]     = aU[i].x;
            dst[pkidx(row, 2 * kq + 1)] = aU[i].y;
        }
    };

    cp_b(0, 0);
    cp_b(1, 1);
    load_a(0);
    sts_a(0);
    cp_wait<0>();
    __syncthreads();

    int lane = tid & 31, w = tid >> 5;
    int la3 = lane & 3, lg = lane >> 2;
    int axor = 4 * (la3 ^ (lg & 3));
    const int aOff = lg * 16 + axor;
    const int bOff = (w * 32 + lg) * 16 + axor;

    float acc[4][4][4];
#pragma unroll
    for (int mt = 0; mt < 4; mt++)
#pragma unroll
        for (int nt = 0; nt < 4; nt++)
#pragma unroll
            for (int r = 0; r < 4; r++) acc[mt][nt][r] = 0.f;

    for (int c = 0; c < 8; c++) {
        int st = c & 1;
        const uint32_t* As = sm + st * 1024;
        const uint32_t* Bs = sm + G_SOFF_B + st * 4096;

        uint4 Vb[4];
#pragma unroll
        for (int nt = 0; nt < 4; nt++)
            Vb[nt] = *(const uint4*)&Bs[bOff + nt * 128];
#pragma unroll
        for (int mt = 0; mt < 2; mt++) {
            uint4 U0 = *(const uint4*)&As[aOff + mt * 256];
            uint4 U1 = *(const uint4*)&As[aOff + mt * 256 + 128];
            uint32_t a0[4] = {U0.x, U1.x, U0.y, U1.y};
            uint32_t a1[4] = {U0.z, U1.z, U0.w, U1.w};
#pragma unroll
            for (int nt = 0; nt < 4; nt++)
                mma_f16(acc[mt][nt], a0, Vb[nt].x, Vb[nt].y);
#pragma unroll
            for (int nt = 0; nt < 4; nt++)
                mma_f16(acc[mt][nt], a1, Vb[nt].z, Vb[nt].w);
        }
        if (c < 7) load_a((c + 1) * 32);
#pragma unroll
        for (int mt = 2; mt < 4; mt++) {
            uint4 U0 = *(const uint4*)&As[aOff + mt * 256];
            uint4 U1 = *(const uint4*)&As[aOff + mt * 256 + 128];
            uint32_t a0[4] = {U0.x, U1.x, U0.y, U1.y};
            uint32_t a1[4] = {U0.z, U1.z, U0.w, U1.w};
#pragma unroll
            for (int nt = 0; nt < 4; nt++)
                mma_f16(acc[mt][nt], a0, Vb[nt].x, Vb[nt].y);
#pragma unroll
            for (int nt = 0; nt < 4; nt++)
                mma_f16(acc[mt][nt], a1, Vb[nt].z, Vb[nt].w);
        }
        if (c < 7) sts_a(st ^ 1);
        cp_wait<0>();
        __syncthreads();
        if (c + 2 < 8) cp_b(st, c + 2);
    }

#pragma unroll
    for (int mt = 0; mt < 4; mt++) {
        int row0 = rowBase + mt * 16 + lg;
#pragma unroll
        for (int nt = 0; nt < 4; nt++) {
            int col = w * 32 + nt * 8 + 2 * la3;
            float b0 = bias_s[col], b1 = bias_s[col + 1];
            O16[(size_t)row0 * 128 + (col >> 1)] =
                f16pk(acc[mt][nt][0] + b0, acc[mt][nt][1] + b1);
            O16[(size_t)(row0 + 8) * 128 + (col >> 1)] =
                f16pk(acc[mt][nt][2] + b0, acc[mt][nt][3] + b1);
        }
    }
}

// --------------- persistent weight-stationary FINAL GEMM --------------------
__global__ void __launch_bounds__(512, 1)
gemm_final(const uint32_t* __restrict__ A16, const uint32_t* __restrict__ Bpk,
           const float* __restrict__ bias, float* __restrict__ Out) {
    extern __shared__ uint32_t sm[];
    float* fx = (float*)(sm + P_SOFF_FX);
    float* bias_s = fx;
    float* s2_s   = fx + 256;
    float* t2_s   = fx + 512;
    int tid = threadIdx.x;
    if (tid < 256) {
        bias_s[tid] = bias[tid];
        s2_s[tid]   = g_s2[tid];
        t2_s[tid]   = g_t2[tid];
    }
    uint32_t smemB = smem_u32(sm);
#pragma unroll
    for (int i = 0; i < 16; i++) {
        int o = (tid + i * 512) * 4;
        int c = o >> 12, within = o & 4095;
        int nb = within >> 11, idx = within & 2047;
        cp16(smemB + (uint32_t)o * 4u,
             Bpk + (size_t)(nb * 8 + c) * 2048 + idx);
    }
    cp_commit();
    cp_wait<0>();
    __syncthreads();

    int lane = tid & 31, w = tid >> 5;
    int wm = w & 1, wn = w >> 1;
    int la3 = lane & 3, lg = lane >> 2;
    int axor = 4 * (la3 ^ (lg & 3));
    const int bOff = (wn * 32 + lg) * 16 + axor;
    const int aOff = (wm * 64 + lg) * 16 + axor;

    for (int t = blockIdx.x; t < R_ / 128; t += gridDim.x) {
        int rowBase = t * 128;
#pragma unroll
        for (int i = 0; i < 16; i++) {
            int f = tid + i * 512;
            int c = f >> 10, r = f & 1023, row = r >> 3, kq = r & 7;
            uint2 u = *(const uint2*)&A16[(size_t)(rowBase + row) * 128 + c * 16 + kq * 2];
            float2 f0 = upk(u.x), f1 = upk(u.y);
            int k = c * 32 + kq * 4;
            float x0 = fmaxf(fmaf(f0.x, s2_s[k],     t2_s[k]),     0.f);
            float x1 = fmaxf(fmaf(f0.y, s2_s[k + 1], t2_s[k + 1]), 0.f);
            float x2 = fmaxf(fmaf(f1.x, s2_s[k + 2], t2_s[k + 2]), 0.f);
            float x3 = fmaxf(fmaf(f1.y, s2_s[k + 3], t2_s[k + 3]), 0.f);
            uint32_t* dst = sm + P_SOFF_A + c * 2048;
            dst[pkidx(row, 2 * kq)]     = f16pk(x0, x1);
            dst[pkidx(row, 2 * kq + 1)] = f16pk(x2, x3);
        }
        __syncthreads();

        float acc[4][4][4];
#pragma unroll
        for (int mt = 0; mt < 4; mt++)
#pragma unroll
            for (int nt = 0; nt < 4; nt++)
#pragma unroll
                for (int r = 0; r < 4; r++) acc[mt][nt][r] = 0.f;

#pragma unroll
        for (int c = 0; c < 8; c++) {
            const uint32_t* As = sm + P_SOFF_A + c * 2048;
            const uint32_t* Bs = sm + c * 4096;
            uint4 Vb[4];
#pragma unroll
            for (int nt = 0; nt < 4; nt++)
                Vb[nt] = *(const uint4*)&Bs[bOff + nt * 128];
#pragma unroll
            for (int mt = 0; mt < 4; mt++) {
                uint4 U0 = *(const uint4*)&As[aOff + mt * 256];
                uint4 U1 = *(const uint4*)&As[aOff + mt * 256 + 128];
                uint32_t a0[4] = {U0.x, U1.x, U0.y, U1.y};
                uint32_t a1[4] = {U0.z, U1.z, U0.w, U1.w};
#pragma unroll
                for (int nt = 0; nt < 4; nt++)
                    mma_f16(acc[mt][nt], a0, Vb[nt].x, Vb[nt].y);
#pragma unroll
                for (int nt = 0; nt < 4; nt++)
                    mma_f16(acc[mt][nt], a1, Vb[nt].z, Vb[nt].w);
            }
        }
        __syncthreads();

#pragma unroll
        for (int mt = 0; mt < 4; mt++) {
            int row0 = rowBase + wm * 64 + mt * 16 + lg;
#pragma unroll
            for (int nt = 0; nt < 4; nt++) {
                int col = wn * 32 + nt * 8 + 2 * la3;
                float b0 = bias_s[col], b1 = bias_s[col + 1];
                *(float2*)&Out[(size_t)row0 * 256 + col] =
                    make_float2(acc[mt][nt][0] + b0, acc[mt][nt][1] + b1);
                *(float2*)&Out[(size_t)(row0 + 8) * 256 + col] =
                    make_float2(acc[mt][nt][2] + b0, acc[mt][nt][3] + b1);
            }
        }
    }
}

// ----------------------- fused produce+attention kernel ---------------------
// 256 threads, 8 col-warps, 64-row tile, occupancy 2.
// EPI: 0 = qk = q-k ; 1 = va = dm*qk ; 2 = va += db ; 3 = we = omega*v
template <int EPI, bool POS>
__device__ __noinline__ void run_subpass(
    uint32_t* sm, int tid, int rowBase,
    const float* __restrict__ nf,
    const uint32_t* __restrict__ Bmat,
    const float* bias_s, const float* w1f_s, const float* b1f_s,
    const float* diff_s, int blockId) {

    uint32_t smemB_addr = smem_u32(sm + FS_BSTG);
    auto cp_b = [&](int stage, int c) {
        uint32_t dstb = smemB_addr + (uint32_t)stage * 16384u;
#pragma unroll
        for (int i = 0; i < 4; i++) {
            int off = (tid + i * 256) * 4;
            const uint32_t* src = (off < 2048)
                ? Bmat + (size_t)c * 2048 + off
                : Bmat + (size_t)(8 + c) * 2048 + (off - 2048);
            cp16(dstb + (uint32_t)off * 4u, src);
        }
        cp_commit();
    };

    uint2 aU[2];
    auto load_a = [&](int kb) {
#pragma unroll
        for (int i = 0; i < 2; i++) {
            int f = tid + i * 256, row = f >> 3, kq = f & 7;
            if (POS) {
                float d0 = diff_s[row * 4], d1 = diff_s[row * 4 + 1],
                      d2 = diff_s[row * 4 + 2];
                float t[4];
#pragma unroll
                for (int j = 0; j < 4; j++) {
                    int k = kb + kq * 4 + j;
                    float h = fmaf(d0, w1f_s[k * 3],
                              fmaf(d1, w1f_s[k * 3 + 1],
                              fmaf(d2, w1f_s[k * 3 + 2], b1f_s[k])));
                    t[j] = fmaxf(h, 0.f);
                }
                aU[i].x = f16pk(t[0], t[1]);
                aU[i].y = f16pk(t[2], t[3]);
            } else {
                float4 v = *(const float4*)&nf[(size_t)(rowBase + row) * 256 + kb + kq * 4];
                aU[i].x = f16pk(v.x, v.y);
                aU[i].y = f16pk(v.z, v.w);
            }
        }
    };
    auto sts_a = [&](int stage) {
        uint32_t* dst = sm + FS_ASTG + stage * 1024;
#pragma unroll
        for (int i = 0; i < 2; i++) {
            int f = tid + i * 256, row = f >> 3, kq = f & 7;
            dst[pkidx(row, 2 * kq)]     = aU[i].x;
            dst[pkidx(row, 2 * kq + 1)] = aU[i].y;
        }
    };

    cp_b(0, 0);
    cp_b(1, 1);
    load_a(0);
    sts_a(0);
    cp_wait<0>();
    __syncthreads();

    int lane = tid & 31, w = tid >> 5;
    int la3 = lane & 3, lg = lane >> 2;
    int axor = 4 * (la3 ^ (lg & 3));
    const int aOff = lg * 16 + axor;
    const int bOff = (w * 32 + lg) * 16 + axor;

    float acc[4][4][4];
#pragma unroll
    for (int mt = 0; mt < 4; mt++)
#pragma unroll
        for (int nt = 0; nt < 4; nt++)
#pragma unroll
            for (int r = 0; r < 4; r++) acc[mt][nt][r] = 0.f;

    for (int c = 0; c < 8; c++) {
        int st = c & 1;
        const uint32_t* As = sm + FS_ASTG + st * 1024;
        const uint32_t* Bs = sm + FS_BSTG + st * 4096;

        uint4 Vb[4];
#pragma unroll
        for (int nt = 0; nt < 4; nt++)
            Vb[nt] = *(const uint4*)&Bs[bOff + nt * 128];
#pragma unroll
        for (int mt = 0; mt < 2; mt++) {
            uint4 U0 = *(const uint4*)&As[aOff + mt * 256];
            uint4 U1 = *(const uint4*)&As[aOff + mt * 256 + 128];
            uint32_t a0[4] = {U0.x, U1.x, U0.y, U1.y};
            uint32_t a1[4] = {U0.z, U1.z, U0.w, U1.w};
#pragma unroll
            for (int nt = 0; nt < 4; nt++)
                mma_f16(acc[mt][nt], a0, Vb[nt].x, Vb[nt].y);
#pragma unroll
            for (int nt = 0; nt < 4; nt++)
                mma_f16(acc[mt][nt], a1, Vb[nt].z, Vb[nt].w);
        }
        if (c < 7) load_a((c + 1) * 32);
#pragma unroll
        for (int mt = 2; mt < 4; mt++) {
            uint4 U0 = *(const uint4*)&As[aOff + mt * 256];
            uint4 U1 = *(const uint4*)&As[aOff + mt * 256 + 128];
            uint32_t a0[4] = {U0.x, U1.x, U0.y, U1.y};
            uint32_t a1[4] = {U0.z, U1.z, U0.w, U1.w};
#pragma unroll
            for (int nt = 0; nt < 4; nt++)
                mma_f16(acc[mt][nt], a0, Vb[nt].x, Vb[nt].y);
#pragma unroll
            for (int nt = 0; nt < 4; nt++)
                mma_f16(acc[mt][nt], a1, Vb[nt].z, Vb[nt].w);
        }
        if (c < 7) sts_a(st ^ 1);
        cp_wait<0>();
        __syncthreads();
        if (c + 2 < 8) cp_b(st, c + 2);
    }

    // ---- epilogue ----
    float csum[8], csq[8];
#pragma unroll
    for (int j = 0; j < 8; j++) { csum[j] = 0.f; csq[j] = 0.f; }

#pragma unroll
    for (int mt = 0; mt < 4; mt++) {
        int row0 = mt * 16 + lg;
#pragma unroll
        for (int nt = 0; nt < 4; nt++) {
            int col = w * 32 + nt * 8 + 2 * la3;
            float b0 = bias_s[col], b1 = bias_s[col + 1];
            int vi0 = row0 * 132 + (col >> 1);
            int vi1 = (row0 + 8) * 132 + (col >> 1);
            float a0 = acc[mt][nt][0] + b0, a1 = acc[mt][nt][1] + b1;
            float a2 = acc[mt][nt][2] + b0, a3 = acc[mt][nt][3] + b1;
            if (EPI == 0) {
                float2 qv = upk(sm[FS_Q + mt * 128 + (col >> 1)]);
                sm[FS_VA + vi0] = f16pk(qv.x - a0, qv.y - a1);
                sm[FS_VA + vi1] = f16pk(qv.x - a2, qv.y - a3);
            } else if (EPI == 1) {
                float2 u0 = upk(sm[FS_VA + vi0]), u1 = upk(sm[FS_VA + vi1]);
                sm[FS_VA + vi0] = f16pk(a0 * u0.x, a1 * u0.y);
                sm[FS_VA + vi1] = f16pk(a2 * u1.x, a3 * u1.y);
            } else if (EPI == 2) {
                float2 u0 = upk(sm[FS_VA + vi0]), u1 = upk(sm[FS_VA + vi1]);
                sm[FS_VA + vi0] = f16pk(u0.x + a0, u0.y + a1);
                sm[FS_VA + vi1] = f16pk(u1.x + a2, u1.y + a3);
            } else {
                const float* om = (const float*)(sm + FS_OM);
                float o0 = om[row0 * 36 + (col >> 3)];
                float o1 = om[(row0 + 8) * 36 + (col >> 3)];
                float w00 = o0 * a0, w01 = o0 * a1;
                float w10 = o1 * a2, w11 = o1 * a3;
                g_we16[(size_t)(rowBase + row0) * 128 + (col >> 1)]     = f16pk(w00, w01);
                g_we16[(size_t)(rowBase + row0 + 8) * 128 + (col >> 1)] = f16pk(w10, w11);
                csum[nt * 2]     += w00 + w10;
                csum[nt * 2 + 1] += w01 + w11;
                csq[nt * 2]      += w00 * w00 + w10 * w10;
                csq[nt * 2 + 1]  += w01 * w01 + w11 * w11;
            }
        }
    }
    if (EPI == 3) {
#pragma unroll
        for (int j = 0; j < 8; j++) {
#pragma unroll
            for (int off = 4; off < 32; off <<= 1) {
                csum[j] += __shfl_xor_sync(0xffffffffu, csum[j], off);
                csq[j]  += __shfl_xor_sync(0xffffffffu, csq[j],  off);
            }
        }
        if (lg == 0) {
#pragma unroll
            for (int u = 0; u < 8; u++) {
                int nt = u >> 1, uu = u & 1;
                int col = w * 32 + nt * 8 + 2 * la3 + uu;
                g_part2[(size_t)blockId * 512 + col]       = csum[u];
                g_part2[(size_t)blockId * 512 + 256 + col] = csq[u];
            }
        }
        __syncthreads();
    } else {
        __syncthreads();
    }
}

__global__ void __launch_bounds__(256, 2)
fused_kernel(const float* __restrict__ nf, const float* __restrict__ pts,
             const float* __restrict__ nbr,
             const float* __restrict__ k_b, const float* __restrict__ dm_b2,
             const float* __restrict__ db_b2, const float* __restrict__ v_b,
             const float* __restrict__ convw) {
    extern __shared__ uint32_t sm[];
    float* fx = (float*)(sm + FS_FX);
    int tid = threadIdx.x;
    int rowBase = blockIdx.x * 64;

    fx[FXF_KB + tid]  = k_b[tid];
    fx[FXF_DMB + tid] = dm_b2[tid];
    fx[FXF_DBB + tid] = db_b2[tid];
    fx[FXF_VB + tid]  = v_b[tid];
    fx[FXF_B1F + tid]       = g_b1f[0][tid];
    fx[FXF_B1F + 256 + tid] = g_b1f[1][tid];
    for (int i = tid; i < 1024; i += 256) fx[FXF_CW + i] = convw[i];
    for (int i = tid; i < 768; i += 256) {
        fx[FXF_W1F + i]       = g_w1f[0][i];
        fx[FXF_W1F + 768 + i] = g_w1f[1][i];
    }
    if (tid < 64) {
        int r = rowBase + tid, bn = r >> 4;
        fx[FXF_DIFF + tid * 4 + 0] = pts[bn * 3 + 0] - nbr[(size_t)r * 3 + 0];
        fx[FXF_DIFF + tid * 4 + 1] = pts[bn * 3 + 1] - nbr[(size_t)r * 3 + 1];
        fx[FXF_DIFF + tid * 4 + 2] = pts[bn * 3 + 2] - nbr[(size_t)r * 3 + 2];
    }
    {
        int bnb = rowBase >> 4;
        for (int i = tid; i < 512; i += 256) sm[FS_Q + i] = g_q16[bnb * 128 + i];
    }
    __syncthreads();

    const uint32_t* BK  = g_Bpk + 1 * 32768;
    const uint32_t* BV  = g_Bpk + 2 * 32768;
    const uint32_t* BDM = g_Bpk + 3 * 32768;
    const uint32_t* BDB = g_Bpk + 4 * 32768;
    const float* diff_s = fx + FXF_DIFF;

    run_subpass<0, false>(sm, tid, rowBase, nf, BK,  fx + FXF_KB,  nullptr, nullptr, diff_s, blockIdx.x);
    run_subpass<1, true >(sm, tid, rowBase, nf, BDM, fx + FXF_DMB, fx + FXF_W1F,       fx + FXF_B1F,       diff_s, blockIdx.x);
    run_subpass<2, true >(sm, tid, rowBase, nf, BDB, fx + FXF_DBB, fx + FXF_W1F + 768, fx + FXF_B1F + 256, diff_s, blockIdx.x);

    // ---- attention: va -> omega ----
    __syncthreads();
    {
        int l = tid & 31, w = tid >> 5;
        float cwr[32];
#pragma unroll
        for (int i = 0; i < 32; i++)
            cwr[i] = fx[FXF_CW + (l >> 2) * 128 + (l & 3) * 32 + i];
        float* om = (float*)(sm + FS_OM);
        int gb = (l >> 2) * 16;
        for (int it = 0; it < 8; it++) {
            int row = w * 8 + it;
            const uint32_t* vrow = sm + FS_VA + row * 132;
            float acc = 0.f;
#pragma unroll
            for (int t = 0; t < 16; t += 2) {
                uint2 u = *(const uint2*)&vrow[gb + t];
                float2 f0 = upk(u.x), f1 = upk(u.y);
                int i0 = t * 2;
                acc = fmaf(f0.x, cwr[i0], acc);
                acc = fmaf(f0.y, cwr[i0 + 1], acc);
                acc = fmaf(f1.x, cwr[i0 + 2], acc);
                acc = fmaf(f1.y, cwr[i0 + 3], acc);
            }
            float mx = acc;
#pragma unroll
            for (int off = 16; off > 0; off >>= 1)
                mx = fmaxf(mx, __shfl_xor_sync(0xffffffffu, mx, off));
            float e = expf(acc - mx);
            float ss = e;
#pragma unroll
            for (int off = 16; off > 0; off >>= 1)
                ss += __shfl_xor_sync(0xffffffffu, ss, off);
            om[row * 36 + l] = e / ss;
        }
    }
    __syncthreads();

    run_subpass<3, false>(sm, tid, rowBase, nf, BV, fx + FXF_VB, nullptr, nullptr, diff_s, blockIdx.x);
}

// --------------------------- BN2 reductions --------------------------------
__global__ void reduce_part2() {
    int b = blockIdx.x, tid = threadIdx.x;
    for (int c = tid; c < 512; c += 256) {
        float s = 0.f;
#pragma unroll 8
        for (int i = 0; i < 64; i++)
            s += g_part2[(size_t)(b * 64 + i) * 512 + c];
        g_part2r[b * 512 + c] = s;
    }
}

__global__ void finalize2_kernel(const float* __restrict__ bn_g,
                                 const float* __restrict__ bn_b) {
    int c = threadIdx.x;
    float s = 0.f, sq = 0.f;
    for (int b = 0; b < 64; b++) {
        s  += g_part2r[b * 512 + c];
        sq += g_part2r[b * 512 + 256 + c];
    }
    float mean = s / (float)R_;
    float var = sq / (float)R_ - mean * mean;
    float sc = bn_g[c] * rsqrtf(var + EPSV);
    g_s2[c] = sc;
    g_t2[c] = bn_b[c] - mean * sc;
}

// ------------------------------- launch -------------------------------------
extern "C" void kernel_launch(void* const* d_in, const int* in_sizes, int n_in,
                              void* d_out, int out_size) {
    const float* pts   = (const float*)d_in[0];
    const float* pf    = (const float*)d_in[1];
    const float* nbr   = (const float*)d_in[2];
    const float* nf    = (const float*)d_in[3];
    const float* dm_w1 = (const float*)d_in[4];
    const float* dm_b1 = (const float*)d_in[5];
    const float* dm_w2 = (const float*)d_in[6];
    const float* dm_b2 = (const float*)d_in[7];
    const float* dm_g  = (const float*)d_in[8];
    const float* dm_be = (const float*)d_in[9];
    const float* db_w1 = (const float*)d_in[10];
    const float* db_b1 = (const float*)d_in[11];
    const float* db_w2 = (const float*)d_in[12];
    const float* db_b2 = (const float*)d_in[13];
    const float* db_g  = (const float*)d_in[14];
    const float* db_be = (const float*)d_in[15];
    const float* q_w   = (const float*)d_in[16];
    const float* q_b   = (const float*)d_in[17];
    const float* k_w   = (const float*)d_in[18];
    const float* k_b   = (const float*)d_in[19];
    const float* v_w   = (const float*)d_in[20];
    const float* v_b   = (const float*)d_in[21];
    const float* convw = (const float*)d_in[22];
    const float* bn_g  = (const float*)d_in[23];
    const float* bn_b  = (const float*)d_in[24];
    const float* lin_w = (const float*)d_in[25];
    const float* lin_b = (const float*)d_in[26];
    float* out = (float*)d_out;

    void *p_q, *p_we, *p_bpk;
    cudaGetSymbolAddress(&p_q,   g_q16);
    cudaGetSymbolAddress(&p_we,  g_we16);
    cudaGetSymbolAddress(&p_bpk, g_Bpk);
    const uint32_t* Bpk = (const uint32_t*)p_bpk;

    cudaFuncSetAttribute(gemm_q,
                         cudaFuncAttributeMaxDynamicSharedMemorySize, G_DYN_SMEM);
    cudaFuncSetAttribute(gemm_final,
                         cudaFuncAttributeMaxDynamicSharedMemorySize, P_DYN_SMEM);
    cudaFuncSetAttribute(fused_kernel,
                         cudaFuncAttributeMaxDynamicSharedMemorySize, FUSED_SMEM);

    prep_weights<<<dim3(8, 2, 6), 256>>>(q_w, k_w, v_w, dm_w2, db_w2, lin_w);
    diffstats_kernel<<<STAT_BLOCKS, 256>>>(pts, nbr);
    fold_kernel<<<1, 256>>>(dm_w1, dm_b1, dm_g, dm_be, db_w1, db_b1, db_g, db_be);

    gemm_q<<<BNp / 64, 256, G_DYN_SMEM>>>(pf, Bpk + 0 * 32768, q_b,
                                          (uint32_t*)p_q);

    fused_kernel<<<NTILES, 256, FUSED_SMEM>>>(nf, pts, nbr,
                                              k_b, dm_b2, db_b2, v_b, convw);

    reduce_part2<<<64, 256>>>();
    finalize2_kernel<<<1, 256>>>(bn_g, bn_b);

    gemm_final<<<PGRID, 512, P_DYN_SMEM>>>((const uint32_t*)p_we,
                                           Bpk + 5 * 32768, lin_b, out);
}